// round 15
// baseline (speedup 1.0000x reference)
#include <cuda_runtime.h>
#include <cuda_fp16.h>
#include <math.h>

#define BB 8
#define HH 32
#define WW 96
#define NN 3072      // HH*WW
#define CC 64
#define CQK 16
#define KSEL 614
#define CIN0 512
#define BN_EPS 1e-5f

// ---------------- device scratch (static allocation, allowed) ----------------
__device__ float  g_ptab[64*96];        // positional table (c, coord-1)
__device__ float  g_xact[BB*CC*NN];
__device__ float  g_chain[BB*CC*NN];
__device__ float  g_bbuf[BB*CC*NN];
__device__ float  g_bbuf2[BB*CC*NN];
__device__ float  g_qf [BB*NN*CQK];
__device__ float  g_ktf[BB*NN*CQK];
__device__ float  g_vtf[BB*NN*CC];
__device__ __half g_qh [BB*NN*CQK];
__device__ __half g_kh [BB*NN*CQK];
__device__ __half g_vh [BB*NN*CC];
__device__ __half g_att[(size_t)BB*NN*NN];  // 151 MB
__device__ __half g_o16[BB*CC*NN];
__device__ float  g_imp[BB*NN];
__device__ int    g_idx[BB*KSEL];
__device__ float  g_qg[BB*KSEL*CQK];
__device__ float  g_kg[BB*KSEL*CQK];
__device__ float  g_vg[BB*KSEL*CC];
__device__ float  g_ar[(size_t)BB*KSEL*KSEL];

// ---------------- positional table (same per-element double formula) ---------
__global__ void pos_kernel() {
    int i = blockIdx.x*blockDim.x + threadIdx.x;
    if (i >= 64*96) return;
    int c = i / 96, j = i % 96;
    int cc = c & 31;
    int ii = cc >> 1;
    double t = pow(10000.0, (double)ii / 16.0);
    double v = (double)(j+1) / t;
    double r = ((cc & 1) == 0) ? sin(v) : cos(v);
    g_ptab[i] = (float)r;
}

// ---------------- conv 3x3 (pad 1) + BN + ReLU (mask-critical fma chains) ----
// 256 threads: thread = 4 cout x 6 px. Pos added from table (bit-identical).
__global__ __launch_bounds__(256) void conv3x3_kernel(
        const float* __restrict__ xin, float* __restrict__ outp,
        const float* __restrict__ w, const float* __restrict__ bn,
        int Cin, int src, int dst, int flags)
{
    const float* in = (src==0) ? xin : (src==1 ? g_chain : (src==2 ? g_bbuf : g_bbuf2));
    float* out = (dst==0) ? g_xact : (dst==1 ? g_chain : outp);

    int b = blockIdx.x / HH;
    int y = blockIdx.x % HH;
    int t = threadIdx.x;
    int pxg = t & 15, cog = t >> 4;    // 16 px-groups x 16 cout-groups
    int x0 = pxg * 6;

    __shared__ float s_in[8][3][98];
    __shared__ float s_w[8][64][9];
    __shared__ float s_inv[64], s_beta[64];

    if (t < 64) {
        float s = bn[t], bb = bn[64+t], m = bn[128+t], v = bn[192+t];
        float inv = s * rsqrtf(v + BN_EPS);
        s_inv[t] = inv;
        s_beta[t] = bb - m*inv;
    }

    float acc[4][6];
#pragma unroll
    for (int i=0;i<4;i++)
#pragma unroll
        for (int j=0;j<6;j++) acc[i][j]=0.f;

    for (int ci0 = 0; ci0 < Cin; ci0 += 8) {
        __syncthreads();
        for (int i=t; i<2352; i+=256) {
            int cc = i/294; int r = (i%294)/98; int col = i%98;
            int yy = y-1+r; int xx = col-1;
            float v = 0.f;
            if (yy>=0 && yy<HH && xx>=0 && xx<WW)
                v = in[((size_t)(b*Cin + ci0+cc)*HH + yy)*WW + xx];
            s_in[cc][r][col] = v;
        }
        for (int i=t; i<4608; i+=256) {
            int cc = i/576; int rem = i%576; int co = rem/9; int kk = rem%9;
            s_w[cc][co][kk] = w[((size_t)(co*Cin) + ci0+cc)*9 + kk];
        }
        __syncthreads();
#pragma unroll
        for (int cc=0; cc<8; cc++) {
            float iv[3][8];
#pragma unroll
            for (int r=0;r<3;r++)
#pragma unroll
                for (int j=0;j<8;j++)
                    iv[r][j] = s_in[cc][r][x0+j];
#pragma unroll
            for (int co8=0; co8<4; co8++) {
                const float* wp = s_w[cc][cog*4+co8];
                float w9[9];
#pragma unroll
                for (int k=0;k<9;k++) w9[k]=wp[k];
#pragma unroll
                for (int p=0;p<6;p++) {
                    float a = acc[co8][p];
                    a = __fmaf_rn(iv[0][p  ], w9[0], a);
                    a = __fmaf_rn(iv[0][p+1], w9[1], a);
                    a = __fmaf_rn(iv[0][p+2], w9[2], a);
                    a = __fmaf_rn(iv[1][p  ], w9[3], a);
                    a = __fmaf_rn(iv[1][p+1], w9[4], a);
                    a = __fmaf_rn(iv[1][p+2], w9[5], a);
                    a = __fmaf_rn(iv[2][p  ], w9[6], a);
                    a = __fmaf_rn(iv[2][p+1], w9[7], a);
                    a = __fmaf_rn(iv[2][p+2], w9[8], a);
                    acc[co8][p] = a;
                }
            }
        }
    }
#pragma unroll
    for (int co8=0; co8<4; co8++) {
        int co = cog*4 + co8;
        float inv = s_inv[co], beta = s_beta[co];
#pragma unroll
        for (int p=0;p<6;p++) {
            int x = x0 + p;
            float v = __fmaf_rn(acc[co8][p], inv, beta);
            v = fmaxf(v, 0.f);
            if (flags & 1) v += g_ptab[co*96 + ((co<32)? y : x)];
            if (flags & 2) v = __half2float(__float2half(v));
            out[((size_t)(b*CC + co)*HH + y)*WW + x] = v;
        }
    }
}

// ---------------- QKV projection ----------------------------------------------
__global__ void qkv_kernel(const float* __restrict__ qw, const float* __restrict__ qb,
                           const float* __restrict__ kw, const float* __restrict__ kb,
                           const float* __restrict__ vw, const float* __restrict__ vb)
{
    int b = blockIdx.y;
    int n0 = blockIdx.x * 64;
    int t = threadIdx.x;
    int nt = t & 63, og = t >> 6;     // 4 output groups of 24

    __shared__ float s_x[64][64];
    __shared__ float s_w[96][64];
    __shared__ float s_b[96];

    for (int i=t; i<64*64; i+=256) {
        int c = i>>6, nn2 = i&63;
        s_x[c][nn2] = g_xact[((size_t)(b*CC+c))*NN + n0 + nn2];
    }
    for (int i=t; i<96*64; i+=256) {
        int o = i>>6, c = i&63;
        float wv;
        if (o < 16)      wv = qw[o*64+c];
        else if (o < 32) wv = kw[(o-16)*64+c];
        else             wv = vw[(o-32)*64+c];
        s_w[o][c] = wv;
    }
    if (t < 96) s_b[t] = (t<16)? qb[t] : (t<32 ? kb[t-16] : vb[t-32]);
    __syncthreads();

    float xv[64];
#pragma unroll
    for (int c=0;c<64;c++) xv[c] = s_x[c][nt];

    int n = n0 + nt;
    for (int oi=0; oi<24; oi++) {
        int o = og*24 + oi;
        float a = s_b[o];
#pragma unroll
        for (int c4=0;c4<16;c4++) {
            float4 wv4 = *reinterpret_cast<const float4*>(&s_w[o][c4*4]);
            a = __fmaf_rn(wv4.x, xv[c4*4+0], a);
            a = __fmaf_rn(wv4.y, xv[c4*4+1], a);
            a = __fmaf_rn(wv4.z, xv[c4*4+2], a);
            a = __fmaf_rn(wv4.w, xv[c4*4+3], a);
        }
        if (o < 16) {
            g_qf[((size_t)(b*NN)+n)*CQK + o] = a;
            g_qh[((size_t)(b*NN)+n)*CQK + o] = __float2half(a);
        } else if (o < 32) {
            int oo = o-16;
            g_ktf[((size_t)(b*NN)+n)*CQK + oo] = a;
            g_kh [((size_t)(b*NN)+n)*CQK + oo] = __float2half(a);
        } else {
            int oo = o-32;
            g_vtf[((size_t)(b*NN)+n)*CC + oo] = a;
            g_vh [((size_t)(b*NN)+n)*CC + oo] = __float2half(a);
        }
    }
}

// ---------------- fused energy(fp16) + softmax(fp32) -> att(fp16) ------------
// Round-10 passing version (bit-frozen for the mask path).
__global__ __launch_bounds__(128) void attn_kernel()
{
    int b = blockIdx.y;
    int q0 = blockIdx.x * 2;
    int t = threadIdx.x;
    int lane = t & 31, wid = t >> 5;

    __shared__ float s_q[2][16];
    __shared__ float s_red[2][4];

    if (t < 32) s_q[t>>4][t&15] =
        __half2float(g_qh[((size_t)(b*NN)+q0+(t>>4))*CQK + (t&15)]);
    __syncthreads();
    float qa[16], qb[16];
#pragma unroll
    for (int c=0;c<16;c++) { qa[c]=s_q[0][c]; qb[c]=s_q[1][c]; }

    float ev0[24], ev1[24];
    float lmax0 = -1e30f, lmax1 = -1e30f;
    const int4* kp = reinterpret_cast<const int4*>(&g_kh[((size_t)(b*NN)+t)*CQK]);
#pragma unroll
    for (int i=0;i<24;i++) {
        int4 r0 = kp[0], r1 = kp[1];
        kp += 256;   // 128 rows * 32B / 16B
        __half h[16];
        *reinterpret_cast<int4*>(&h[0]) = r0;
        *reinterpret_cast<int4*>(&h[8]) = r1;
        float a0 = 0.f, a1 = 0.f;
#pragma unroll
        for (int c=0;c<16;c++) {
            float hf = __half2float(h[c]);
            a0 = __fmaf_rn(qa[c], hf, a0);
            a1 = __fmaf_rn(qb[c], hf, a1);
        }
        a0 = __half2float(__float2half(a0));   // energy stored as fp16 in ref
        a1 = __half2float(__float2half(a1));
        ev0[i] = a0; ev1[i] = a1;
        lmax0 = fmaxf(lmax0, a0);
        lmax1 = fmaxf(lmax1, a1);
    }
#pragma unroll
    for (int off=16;off;off>>=1) {
        lmax0 = fmaxf(lmax0, __shfl_xor_sync(0xFFFFFFFFu, lmax0, off));
        lmax1 = fmaxf(lmax1, __shfl_xor_sync(0xFFFFFFFFu, lmax1, off));
    }
    if (lane==0) { s_red[0][wid]=lmax0; s_red[1][wid]=lmax1; }
    __syncthreads();
    float gmax0 = fmaxf(fmaxf(s_red[0][0],s_red[0][1]),fmaxf(s_red[0][2],s_red[0][3]));
    float gmax1 = fmaxf(fmaxf(s_red[1][0],s_red[1][1]),fmaxf(s_red[1][2],s_red[1][3]));
    __syncthreads();

    float lsum0 = 0.f, lsum1 = 0.f;
#pragma unroll
    for (int i=0;i<24;i++) {
        float p0 = expf(ev0[i]-gmax0); ev0[i]=p0; lsum0+=p0;
        float p1 = expf(ev1[i]-gmax1); ev1[i]=p1; lsum1+=p1;
    }
#pragma unroll
    for (int off=16;off;off>>=1) {
        lsum0 += __shfl_xor_sync(0xFFFFFFFFu, lsum0, off);
        lsum1 += __shfl_xor_sync(0xFFFFFFFFu, lsum1, off);
    }
    if (lane==0) { s_red[0][wid]=lsum0; s_red[1][wid]=lsum1; }
    __syncthreads();
    float gsum0 = s_red[0][0]+s_red[0][1]+s_red[0][2]+s_red[0][3];
    float gsum1 = s_red[1][0]+s_red[1][1]+s_red[1][2]+s_red[1][3];

    __half* ap0 = &g_att[((size_t)(b*NN)+q0  )*NN + t];
    __half* ap1 = &g_att[((size_t)(b*NN)+q0+1)*NN + t];
#pragma unroll
    for (int i=0;i<24;i++) {
        ap0[i*128] = __float2half(ev0[i]/gsum0);
        ap1[i*128] = __float2half(ev1[i]/gsum1);
    }
}

// ---------------- out16 = V(fp16) @ att^T(fp16) via HMMA ----------------------
// Register-prefetch pipeline: next tile loaded into registers (LDG) while the
// MMA consumes the current smem tile. Single smem buffer; same data layout
// and MMA chain order as the round-10/13 passing kernel -> o16 bits unchanged.
__global__ __launch_bounds__(256) void out16_kernel()
{
    int b = blockIdx.y;
    int q0 = blockIdx.x * 64;
    int t = threadIdx.x, lane = t & 31, warp = t >> 5;
    int wc = warp & 3;        // c tile: 16 rows
    int wq = warp >> 2;       // q half: 32 cols

    __shared__ __half s_v[64][72];
    __shared__ __half s_a[64][72];
    unsigned svb = (unsigned)__cvta_generic_to_shared(&s_v[0][0]);
    unsigned sab = (unsigned)__cvta_generic_to_shared(&s_a[0][0]);

    float d[4][4];
#pragma unroll
    for (int i=0;i<4;i++)
#pragma unroll
        for (int j=0;j<4;j++) d[i][j]=0.f;

    int mrelA = (lane & 7) + ((lane >> 4) << 3);
    int crelA = wc*16 + ((lane >> 3) & 1) * 8;
    int qrelB = wq*32 + (lane & 7);
    int mrelB = ((lane >> 3) & 1) * 8;

    int row0 = t >> 3, seg = t & 7;    // i = t
    int row1 = row0 + 32;              // i = t + 256

    int4 rv0, rv1, ra0, ra1;
    rv0 = *reinterpret_cast<const int4*>(&g_vh[((size_t)(b*NN)+row0)*CC + seg*8]);
    rv1 = *reinterpret_cast<const int4*>(&g_vh[((size_t)(b*NN)+row1)*CC + seg*8]);
    ra0 = *reinterpret_cast<const int4*>(&g_att[((size_t)(b*NN)+q0+row0)*NN + seg*8]);
    ra1 = *reinterpret_cast<const int4*>(&g_att[((size_t)(b*NN)+q0+row1)*NN + seg*8]);

    for (int it=0; it<48; it++) {
        __syncthreads();
        *reinterpret_cast<int4*>(&s_v[row0][seg*8]) = rv0;
        *reinterpret_cast<int4*>(&s_v[row1][seg*8]) = rv1;
        *reinterpret_cast<int4*>(&s_a[row0][seg*8]) = ra0;
        *reinterpret_cast<int4*>(&s_a[row1][seg*8]) = ra1;
        __syncthreads();
        if (it+1 < 48) {
            int m1 = (it+1)*64;
            rv0 = *reinterpret_cast<const int4*>(&g_vh[((size_t)(b*NN)+m1+row0)*CC + seg*8]);
            rv1 = *reinterpret_cast<const int4*>(&g_vh[((size_t)(b*NN)+m1+row1)*CC + seg*8]);
            ra0 = *reinterpret_cast<const int4*>(&g_att[((size_t)(b*NN)+q0+row0)*NN + m1 + seg*8]);
            ra1 = *reinterpret_cast<const int4*>(&g_att[((size_t)(b*NN)+q0+row1)*NN + m1 + seg*8]);
        }
#pragma unroll
        for (int ks=0; ks<4; ks++) {
            int mk = ks*16;
            unsigned aaddr = svb + (unsigned)(((mk + mrelA)*72 + crelA)*2);
            unsigned a0,a1,a2,a3;
            asm volatile("ldmatrix.sync.aligned.m8n8.x4.trans.shared.b16 {%0,%1,%2,%3},[%4];"
                : "=r"(a0),"=r"(a1),"=r"(a2),"=r"(a3) : "r"(aaddr));
#pragma unroll
            for (int nt=0; nt<4; nt++) {
                unsigned baddr = sab + (unsigned)(((qrelB + nt*8)*72 + mk + mrelB)*2);
                unsigned b0,b1;
                asm volatile("ldmatrix.sync.aligned.m8n8.x2.shared.b16 {%0,%1},[%2];"
                    : "=r"(b0),"=r"(b1) : "r"(baddr));
                asm volatile("mma.sync.aligned.m16n8k16.row.col.f32.f16.f16.f32 "
                    "{%0,%1,%2,%3},{%4,%5,%6,%7},{%8,%9},{%0,%1,%2,%3};"
                    : "+f"(d[nt][0]),"+f"(d[nt][1]),"+f"(d[nt][2]),"+f"(d[nt][3])
                    : "r"(a0),"r"(a1),"r"(a2),"r"(a3),"r"(b0),"r"(b1));
            }
        }
    }
    int crow0 = wc*16 + (lane >> 2);
#pragma unroll
    for (int nt=0; nt<4; nt++) {
        int qc = q0 + wq*32 + nt*8 + (lane & 3)*2;
        g_o16[((size_t)(b*CC)+crow0)*NN + qc]       = __float2half(d[nt][0]);
        g_o16[((size_t)(b*CC)+crow0)*NN + qc + 1]   = __float2half(d[nt][1]);
        g_o16[((size_t)(b*CC)+crow0+8)*NN + qc]     = __float2half(d[nt][2]);
        g_o16[((size_t)(b*CC)+crow0+8)*NN + qc + 1] = __float2half(d[nt][3]);
    }
}

// ---------------- importance column sums -------------------------------------
__global__ __launch_bounds__(256) void imp_kernel() {
    int b = blockIdx.y;
    int m0 = blockIdx.x * 256;
    int t = threadIdx.x;
    __shared__ __half s_t[64][256];
    float acc = 0.f;
    for (int n0=0; n0<NN; n0+=64) {
        __syncthreads();
        for (int i=t; i<2048; i+=256) {
            int row = i >> 5, seg = i & 31;
            *reinterpret_cast<int4*>(&s_t[row][seg*8]) =
                *reinterpret_cast<const int4*>(&g_att[((size_t)(b*NN)+n0+row)*NN + m0 + seg*8]);
        }
        __syncthreads();
#pragma unroll 8
        for (int r=0;r<64;r++) acc += __half2float(s_t[r][t]);
    }
    g_imp[b*NN + m0 + t] = acc;
}

// ---------------- per-batch top-k via bitonic sort ----------------------------
__global__ void topk_kernel(float* __restrict__ outmask) {
    int b = blockIdx.x;
    int t = threadIdx.x;
    __shared__ unsigned long long sk[4096];
    for (int i=t;i<4096;i+=1024) {
        unsigned long long key;
        if (i < NN) {
            unsigned short hb = __half_as_ushort(__float2half(g_imp[b*NN+i]));
            key = ((unsigned long long)(0xFFFFu - (unsigned)hb) << 32) | (unsigned)i;
        } else key = 0xFFFFFFFFFFFFFFFFull;
        sk[i]=key;
    }
    __syncthreads();
    for (int k=2;k<=4096;k<<=1) {
        for (int j=k>>1;j>0;j>>=1) {
            for (int i=t;i<4096;i+=1024) {
                int ixj = i ^ j;
                if (ixj > i) {
                    bool up = ((i & k) == 0);
                    unsigned long long a = sk[i], c2 = sk[ixj];
                    if ((a > c2) == up) { sk[i]=c2; sk[ixj]=a; }
                }
            }
            __syncthreads();
        }
    }
    if (t < KSEL) g_idx[b*KSEL + t] = (int)(sk[t] & 0xFFFFFFFFull);
    for (int i=t;i<NN;i+=1024) outmask[b*NN + i] = 0.f;
    __syncthreads();
    if (t < KSEL) outmask[b*NN + (int)(sk[t] & 0xFFFFFFFFull)] = 1.0f;
}

// ---------------- gather q/k/v rows at selected indices -----------------------
__global__ void gather_kernel() {
    int g = blockIdx.x*256 + threadIdx.x;
    if (g >= BB*KSEL*CC) return;
    int c = g % CC; int bj = g / CC;
    int b = bj / KSEL;
    int n = g_idx[bj];
    g_vg[(size_t)bj*CC + c] = g_vtf[((size_t)(b*NN)+n)*CC + c];
    if (c < CQK) {
        g_qg[(size_t)bj*CQK + c] = g_qf [((size_t)(b*NN)+n)*CQK + c];
        g_kg[(size_t)bj*CQK + c] = g_ktf[((size_t)(b*NN)+n)*CQK + c];
    }
}

// ---------------- refinement softmax (fp32) -----------------------------------
__global__ void ar_kernel() {
    int b = blockIdx.y, kq = blockIdx.x;
    int t = threadIdx.x;
    int lane = t & 31, wid = t >> 5;
    __shared__ float s_q[16];
    __shared__ float s_red[4];
    if (t < 16) s_q[t] = g_qg[((size_t)(b*KSEL)+kq)*CQK + t];
    __syncthreads();
    float qv[16];
#pragma unroll
    for (int c=0;c<16;c++) qv[c]=s_q[c];

    float ev[5]; float lmax = -1e30f;
#pragma unroll
    for (int i=0;i<5;i++) {
        int j = t + i*128;
        float a = -1e30f;
        if (j < KSEL) {
            const float* kp = &g_kg[((size_t)(b*KSEL)+j)*CQK];
            a = 0.f;
#pragma unroll
            for (int c=0;c<16;c++) a += qv[c]*kp[c];
        }
        ev[i]=a; lmax = fmaxf(lmax, a);
    }
#pragma unroll
    for (int off=16;off;off>>=1) lmax = fmaxf(lmax, __shfl_xor_sync(0xFFFFFFFFu, lmax, off));
    if (lane==0) s_red[wid]=lmax;
    __syncthreads();
    float gmax = fmaxf(fmaxf(s_red[0],s_red[1]),fmaxf(s_red[2],s_red[3]));
    __syncthreads();
    float lsum = 0.f;
#pragma unroll
    for (int i=0;i<5;i++) {
        int j = t + i*128;
        if (j < KSEL) { float p = expf(ev[i]-gmax); ev[i]=p; lsum+=p; }
    }
#pragma unroll
    for (int off=16;off;off>>=1) lsum += __shfl_xor_sync(0xFFFFFFFFu, lsum, off);
    if (lane==0) s_red[wid]=lsum;
    __syncthreads();
    float gsum = s_red[0]+s_red[1]+s_red[2]+s_red[3];
#pragma unroll
    for (int i=0;i<5;i++) {
        int j = t + i*128;
        if (j < KSEL) g_ar[((size_t)(b*KSEL)+kq)*KSEL + j] = ev[i]/gsum;
    }
}

// ---------------- residual mix ------------------------------------------------
__global__ void mix_kernel(const float* __restrict__ gamma, int mode) {
    int i = blockIdx.x*256 + threadIdx.x;
    if (i >= BB*CC*NN) return;
    float g = gamma[0];
    float o = __half2float(g_o16[i]);
    float x = g_xact[i];
    float b16 = g*o + __half2float(__float2half(x));
    g_bbuf[i] = b16;
    if (mode == 2) g_bbuf2[i] = g*o + x;
}

// ---------------- fp32 refinement: overwrite b32 at top-k columns ------------
__global__ void refine_kernel(const float* __restrict__ gamma) {
    int b = blockIdx.y, kq = blockIdx.x;
    int t = threadIdx.x;  // 64 (= channel)
    __shared__ float s_ar[KSEL];
    for (int i=t;i<KSEL;i+=64) s_ar[i] = g_ar[((size_t)(b*KSEL)+kq)*KSEL+i];
    __syncthreads();
    float acc = 0.f;
    for (int j=0;j<KSEL;j++)
        acc += g_vg[((size_t)(b*KSEL)+j)*CC + t] * s_ar[j];
    int n = g_idx[b*KSEL+kq];
    float g = gamma[0];
    g_bbuf2[((size_t)(b*CC)+t)*NN + n] = g*acc + g_xact[((size_t)(b*CC)+t)*NN + n];
}

// ---------------- launcher ----------------------------------------------------
extern "C" void kernel_launch(void* const* d_in, const int* in_sizes, int n_in,
                              void* d_out, int out_size)
{
    (void)in_sizes; (void)n_in; (void)out_size;
    const float* x = (const float*)d_in[0];
    float* out = (float*)d_out;
    const int S = BB*CC*NN;
    float* out_s16  = out;
    float* out_s32  = out + S;
    float* out_mask = out + 2*S;

    pos_kernel<<<24, 256>>>();

    for (int L=0; L<2; L++) {
        int base = 1 + 11*L;
        const float* pre_w  = (const float*)d_in[base+0];
        const float* pre_bn = (const float*)d_in[base+1];
        const float* qw     = (const float*)d_in[base+2];
        const float* qb     = (const float*)d_in[base+3];
        const float* kw     = (const float*)d_in[base+4];
        const float* kb     = (const float*)d_in[base+5];
        const float* vw     = (const float*)d_in[base+6];
        const float* vb     = (const float*)d_in[base+7];
        const float* fin_w  = (const float*)d_in[base+8];
        const float* fin_bn = (const float*)d_in[base+9];
        const float* gamma  = (const float*)d_in[base+10];

        conv3x3_kernel<<<BB*HH, 256>>>(x, nullptr, pre_w, pre_bn,
                                       (L==0)?CIN0:CC, (L==0)?0:1, 0, 1);
        qkv_kernel<<<dim3(48,8), 256>>>(qw,qb,kw,kb,vw,vb);
        attn_kernel<<<dim3(NN/2,BB), 128>>>();
        out16_kernel<<<dim3(48,8), 256>>>();

        if (L==1) {
            imp_kernel<<<dim3(12,8), 256>>>();
            topk_kernel<<<8, 1024>>>(out_mask);
            gather_kernel<<<(BB*KSEL*CC+255)/256, 256>>>();
            ar_kernel<<<dim3(KSEL,BB), 128>>>();
        }

        mix_kernel<<<(S+255)/256, 256>>>(gamma, (L==1)?2:0);

        conv3x3_kernel<<<BB*HH, 256>>>(nullptr, (L==0)?nullptr:out_s16,
                                       fin_w, fin_bn, CC, 2, (L==0)?1:2, 2);

        if (L==1) {
            refine_kernel<<<dim3(KSEL,BB), 64>>>(gamma);
            conv3x3_kernel<<<BB*HH, 256>>>(nullptr, out_s32,
                                           fin_w, fin_bn, CC, 3, 2, 0);
        }
    }
}

// round 16
// speedup vs baseline: 1.4087x; 1.4087x over previous
#include <cuda_runtime.h>
#include <cuda_fp16.h>
#include <math.h>

#define BB 8
#define HH 32
#define WW 96
#define NN 3072      // HH*WW
#define CC 64
#define CQK 16
#define KSEL 614
#define CIN0 512
#define BN_EPS 1e-5f

// ---------------- device scratch (static allocation, allowed) ----------------
__device__ float  g_ptab[64*96];        // positional table (c, coord-1)
__device__ float  g_xact[BB*CC*NN];
__device__ float  g_chain[BB*CC*NN];
__device__ float  g_bbuf[BB*CC*NN];
__device__ float  g_bbuf2[BB*CC*NN];
__device__ float  g_qf [BB*NN*CQK];
__device__ float  g_ktf[BB*NN*CQK];
__device__ float  g_vtf[BB*NN*CC];
__device__ __half g_qh [BB*NN*CQK];
__device__ __half g_kh [BB*NN*CQK];
__device__ __half g_vh [BB*NN*CC];
__device__ __half g_att[(size_t)BB*NN*NN];  // 151 MB
__device__ __half g_o16[BB*CC*NN];
__device__ float  g_imp[BB*NN];
__device__ int    g_idx[BB*KSEL];
__device__ float  g_qg[BB*KSEL*CQK];
__device__ float  g_kg[BB*KSEL*CQK];
__device__ float  g_vg[BB*KSEL*CC];
__device__ float  g_ar[(size_t)BB*KSEL*KSEL];

// ---------------- positional table (same per-element double formula) ---------
__global__ void pos_kernel() {
    int i = blockIdx.x*blockDim.x + threadIdx.x;
    if (i >= 64*96) return;
    int c = i / 96, j = i % 96;
    int cc = c & 31;
    int ii = cc >> 1;
    double t = pow(10000.0, (double)ii / 16.0);
    double v = (double)(j+1) / t;
    double r = ((cc & 1) == 0) ? sin(v) : cos(v);
    g_ptab[i] = (float)r;
}

// ---------------- conv 3x3 (pad 1) + BN + ReLU (mask-critical fma chains) ----
// Grid = BB*HH*2: block handles one image row x HALF the couts (32).
// 256 threads: thread = 2 cout x 6 px. Ownership remap only — each output's
// (ci0-chunk, cc, tap) __fmaf_rn chain is unchanged -> bit-identical outputs.
__global__ __launch_bounds__(256) void conv3x3_kernel(
        const float* __restrict__ xin, float* __restrict__ outp,
        const float* __restrict__ w, const float* __restrict__ bn,
        int Cin, int src, int dst, int flags)
{
    const float* in = (src==0) ? xin : (src==1 ? g_chain : (src==2 ? g_bbuf : g_bbuf2));
    float* out = (dst==0) ? g_xact : (dst==1 ? g_chain : outp);

    int blk = blockIdx.x;
    int coh = blk & 1;                 // cout half: 0 -> [0,32), 1 -> [32,64)
    int rem = blk >> 1;
    int b = rem / HH;
    int y = rem % HH;
    int t = threadIdx.x;
    int pxg = t & 15, cog = t >> 4;    // 16 px-groups x 16 cout-groups (2 couts each)
    int x0 = pxg * 6;

    __shared__ float s_in[8][3][98];
    __shared__ float s_w[8][32][9];
    __shared__ float s_inv[32], s_beta[32];

    if (t < 32) {
        int co = coh*32 + t;
        float s = bn[co], bb = bn[64+co], m = bn[128+co], v = bn[192+co];
        float inv = s * rsqrtf(v + BN_EPS);
        s_inv[t] = inv;
        s_beta[t] = bb - m*inv;
    }

    float acc[2][6];
#pragma unroll
    for (int i=0;i<2;i++)
#pragma unroll
        for (int j=0;j<6;j++) acc[i][j]=0.f;

    for (int ci0 = 0; ci0 < Cin; ci0 += 8) {
        __syncthreads();
        for (int i=t; i<2352; i+=256) {
            int cc = i/294; int r = (i%294)/98; int col = i%98;
            int yy = y-1+r; int xx = col-1;
            float v = 0.f;
            if (yy>=0 && yy<HH && xx>=0 && xx<WW)
                v = in[((size_t)(b*Cin + ci0+cc)*HH + yy)*WW + xx];
            s_in[cc][r][col] = v;
        }
        for (int i=t; i<2304; i+=256) {
            int cc = i/288; int r2 = i%288; int co = r2/9; int kk = r2%9;
            s_w[cc][co][kk] = w[((size_t)((coh*32+co)*Cin) + ci0+cc)*9 + kk];
        }
        __syncthreads();
#pragma unroll
        for (int cc=0; cc<8; cc++) {
            float iv[3][8];
#pragma unroll
            for (int r=0;r<3;r++)
#pragma unroll
                for (int j=0;j<8;j++)
                    iv[r][j] = s_in[cc][r][x0+j];
#pragma unroll
            for (int co8=0; co8<2; co8++) {
                const float* wp = s_w[cc][cog*2+co8];
                float w9[9];
#pragma unroll
                for (int k=0;k<9;k++) w9[k]=wp[k];
#pragma unroll
                for (int p=0;p<6;p++) {
                    float a = acc[co8][p];
                    a = __fmaf_rn(iv[0][p  ], w9[0], a);
                    a = __fmaf_rn(iv[0][p+1], w9[1], a);
                    a = __fmaf_rn(iv[0][p+2], w9[2], a);
                    a = __fmaf_rn(iv[1][p  ], w9[3], a);
                    a = __fmaf_rn(iv[1][p+1], w9[4], a);
                    a = __fmaf_rn(iv[1][p+2], w9[5], a);
                    a = __fmaf_rn(iv[2][p  ], w9[6], a);
                    a = __fmaf_rn(iv[2][p+1], w9[7], a);
                    a = __fmaf_rn(iv[2][p+2], w9[8], a);
                    acc[co8][p] = a;
                }
            }
        }
    }
#pragma unroll
    for (int co8=0; co8<2; co8++) {
        int col = cog*2 + co8;
        int co = coh*32 + col;
        float inv = s_inv[col], beta = s_beta[col];
#pragma unroll
        for (int p=0;p<6;p++) {
            int x = x0 + p;
            float v = __fmaf_rn(acc[co8][p], inv, beta);
            v = fmaxf(v, 0.f);
            if (flags & 1) v += g_ptab[co*96 + ((co<32)? y : x)];
            if (flags & 2) v = __half2float(__float2half(v));
            out[((size_t)(b*CC + co)*HH + y)*WW + x] = v;
        }
    }
}

// ---------------- QKV projection ----------------------------------------------
__global__ void qkv_kernel(const float* __restrict__ qw, const float* __restrict__ qb,
                           const float* __restrict__ kw, const float* __restrict__ kb,
                           const float* __restrict__ vw, const float* __restrict__ vb)
{
    int b = blockIdx.y;
    int n0 = blockIdx.x * 64;
    int t = threadIdx.x;
    int nt = t & 63, og = t >> 6;     // 4 output groups of 24

    __shared__ float s_x[64][64];
    __shared__ float s_w[96][64];
    __shared__ float s_b[96];

    for (int i=t; i<64*64; i+=256) {
        int c = i>>6, nn2 = i&63;
        s_x[c][nn2] = g_xact[((size_t)(b*CC+c))*NN + n0 + nn2];
    }
    for (int i=t; i<96*64; i+=256) {
        int o = i>>6, c = i&63;
        float wv;
        if (o < 16)      wv = qw[o*64+c];
        else if (o < 32) wv = kw[(o-16)*64+c];
        else             wv = vw[(o-32)*64+c];
        s_w[o][c] = wv;
    }
    if (t < 96) s_b[t] = (t<16)? qb[t] : (t<32 ? kb[t-16] : vb[t-32]);
    __syncthreads();

    float xv[64];
#pragma unroll
    for (int c=0;c<64;c++) xv[c] = s_x[c][nt];

    int n = n0 + nt;
    for (int oi=0; oi<24; oi++) {
        int o = og*24 + oi;
        float a = s_b[o];
#pragma unroll
        for (int c4=0;c4<16;c4++) {
            float4 wv4 = *reinterpret_cast<const float4*>(&s_w[o][c4*4]);
            a = __fmaf_rn(wv4.x, xv[c4*4+0], a);
            a = __fmaf_rn(wv4.y, xv[c4*4+1], a);
            a = __fmaf_rn(wv4.z, xv[c4*4+2], a);
            a = __fmaf_rn(wv4.w, xv[c4*4+3], a);
        }
        if (o < 16) {
            g_qf[((size_t)(b*NN)+n)*CQK + o] = a;
            g_qh[((size_t)(b*NN)+n)*CQK + o] = __float2half(a);
        } else if (o < 32) {
            int oo = o-16;
            g_ktf[((size_t)(b*NN)+n)*CQK + oo] = a;
            g_kh [((size_t)(b*NN)+n)*CQK + oo] = __float2half(a);
        } else {
            int oo = o-32;
            g_vtf[((size_t)(b*NN)+n)*CC + oo] = a;
            g_vh [((size_t)(b*NN)+n)*CC + oo] = __float2half(a);
        }
    }
}

// ---------------- fused energy(fp16) + softmax(fp32) -> att(fp16) ------------
// Round-10 passing version (bit-frozen for the mask path).
__global__ __launch_bounds__(128) void attn_kernel()
{
    int b = blockIdx.y;
    int q0 = blockIdx.x * 2;
    int t = threadIdx.x;
    int lane = t & 31, wid = t >> 5;

    __shared__ float s_q[2][16];
    __shared__ float s_red[2][4];

    if (t < 32) s_q[t>>4][t&15] =
        __half2float(g_qh[((size_t)(b*NN)+q0+(t>>4))*CQK + (t&15)]);
    __syncthreads();
    float qa[16], qb[16];
#pragma unroll
    for (int c=0;c<16;c++) { qa[c]=s_q[0][c]; qb[c]=s_q[1][c]; }

    float ev0[24], ev1[24];
    float lmax0 = -1e30f, lmax1 = -1e30f;
    const int4* kp = reinterpret_cast<const int4*>(&g_kh[((size_t)(b*NN)+t)*CQK]);
#pragma unroll
    for (int i=0;i<24;i++) {
        int4 r0 = kp[0], r1 = kp[1];
        kp += 256;   // 128 rows * 32B / 16B
        __half h[16];
        *reinterpret_cast<int4*>(&h[0]) = r0;
        *reinterpret_cast<int4*>(&h[8]) = r1;
        float a0 = 0.f, a1 = 0.f;
#pragma unroll
        for (int c=0;c<16;c++) {
            float hf = __half2float(h[c]);
            a0 = __fmaf_rn(qa[c], hf, a0);
            a1 = __fmaf_rn(qb[c], hf, a1);
        }
        a0 = __half2float(__float2half(a0));   // energy stored as fp16 in ref
        a1 = __half2float(__float2half(a1));
        ev0[i] = a0; ev1[i] = a1;
        lmax0 = fmaxf(lmax0, a0);
        lmax1 = fmaxf(lmax1, a1);
    }
#pragma unroll
    for (int off=16;off;off>>=1) {
        lmax0 = fmaxf(lmax0, __shfl_xor_sync(0xFFFFFFFFu, lmax0, off));
        lmax1 = fmaxf(lmax1, __shfl_xor_sync(0xFFFFFFFFu, lmax1, off));
    }
    if (lane==0) { s_red[0][wid]=lmax0; s_red[1][wid]=lmax1; }
    __syncthreads();
    float gmax0 = fmaxf(fmaxf(s_red[0][0],s_red[0][1]),fmaxf(s_red[0][2],s_red[0][3]));
    float gmax1 = fmaxf(fmaxf(s_red[1][0],s_red[1][1]),fmaxf(s_red[1][2],s_red[1][3]));
    __syncthreads();

    float lsum0 = 0.f, lsum1 = 0.f;
#pragma unroll
    for (int i=0;i<24;i++) {
        float p0 = expf(ev0[i]-gmax0); ev0[i]=p0; lsum0+=p0;
        float p1 = expf(ev1[i]-gmax1); ev1[i]=p1; lsum1+=p1;
    }
#pragma unroll
    for (int off=16;off;off>>=1) {
        lsum0 += __shfl_xor_sync(0xFFFFFFFFu, lsum0, off);
        lsum1 += __shfl_xor_sync(0xFFFFFFFFu, lsum1, off);
    }
    if (lane==0) { s_red[0][wid]=lsum0; s_red[1][wid]=lsum1; }
    __syncthreads();
    float gsum0 = s_red[0][0]+s_red[0][1]+s_red[0][2]+s_red[0][3];
    float gsum1 = s_red[1][0]+s_red[1][1]+s_red[1][2]+s_red[1][3];

    __half* ap0 = &g_att[((size_t)(b*NN)+q0  )*NN + t];
    __half* ap1 = &g_att[((size_t)(b*NN)+q0+1)*NN + t];
#pragma unroll
    for (int i=0;i<24;i++) {
        ap0[i*128] = __float2half(ev0[i]/gsum0);
        ap1[i*128] = __float2half(ev1[i]/gsum1);
    }
}

// ---------------- out16 = V(fp16) @ att^T(fp16) via HMMA ----------------------
// Register-prefetch pipeline (round-15, clock-normalized win). o16 bits
// unchanged vs round-10 chain order.
__global__ __launch_bounds__(256) void out16_kernel()
{
    int b = blockIdx.y;
    int q0 = blockIdx.x * 64;
    int t = threadIdx.x, lane = t & 31, warp = t >> 5;
    int wc = warp & 3;        // c tile: 16 rows
    int wq = warp >> 2;       // q half: 32 cols

    __shared__ __half s_v[64][72];
    __shared__ __half s_a[64][72];
    unsigned svb = (unsigned)__cvta_generic_to_shared(&s_v[0][0]);
    unsigned sab = (unsigned)__cvta_generic_to_shared(&s_a[0][0]);

    float d[4][4];
#pragma unroll
    for (int i=0;i<4;i++)
#pragma unroll
        for (int j=0;j<4;j++) d[i][j]=0.f;

    int mrelA = (lane & 7) + ((lane >> 4) << 3);
    int crelA = wc*16 + ((lane >> 3) & 1) * 8;
    int qrelB = wq*32 + (lane & 7);
    int mrelB = ((lane >> 3) & 1) * 8;

    int row0 = t >> 3, seg = t & 7;    // i = t
    int row1 = row0 + 32;              // i = t + 256

    int4 rv0, rv1, ra0, ra1;
    rv0 = *reinterpret_cast<const int4*>(&g_vh[((size_t)(b*NN)+row0)*CC + seg*8]);
    rv1 = *reinterpret_cast<const int4*>(&g_vh[((size_t)(b*NN)+row1)*CC + seg*8]);
    ra0 = *reinterpret_cast<const int4*>(&g_att[((size_t)(b*NN)+q0+row0)*NN + seg*8]);
    ra1 = *reinterpret_cast<const int4*>(&g_att[((size_t)(b*NN)+q0+row1)*NN + seg*8]);

    for (int it=0; it<48; it++) {
        __syncthreads();
        *reinterpret_cast<int4*>(&s_v[row0][seg*8]) = rv0;
        *reinterpret_cast<int4*>(&s_v[row1][seg*8]) = rv1;
        *reinterpret_cast<int4*>(&s_a[row0][seg*8]) = ra0;
        *reinterpret_cast<int4*>(&s_a[row1][seg*8]) = ra1;
        __syncthreads();
        if (it+1 < 48) {
            int m1 = (it+1)*64;
            rv0 = *reinterpret_cast<const int4*>(&g_vh[((size_t)(b*NN)+m1+row0)*CC + seg*8]);
            rv1 = *reinterpret_cast<const int4*>(&g_vh[((size_t)(b*NN)+m1+row1)*CC + seg*8]);
            ra0 = *reinterpret_cast<const int4*>(&g_att[((size_t)(b*NN)+q0+row0)*NN + m1 + seg*8]);
            ra1 = *reinterpret_cast<const int4*>(&g_att[((size_t)(b*NN)+q0+row1)*NN + m1 + seg*8]);
        }
#pragma unroll
        for (int ks=0; ks<4; ks++) {
            int mk = ks*16;
            unsigned aaddr = svb + (unsigned)(((mk + mrelA)*72 + crelA)*2);
            unsigned a0,a1,a2,a3;
            asm volatile("ldmatrix.sync.aligned.m8n8.x4.trans.shared.b16 {%0,%1,%2,%3},[%4];"
                : "=r"(a0),"=r"(a1),"=r"(a2),"=r"(a3) : "r"(aaddr));
#pragma unroll
            for (int nt=0; nt<4; nt++) {
                unsigned baddr = sab + (unsigned)(((qrelB + nt*8)*72 + mk + mrelB)*2);
                unsigned b0,b1;
                asm volatile("ldmatrix.sync.aligned.m8n8.x2.shared.b16 {%0,%1},[%2];"
                    : "=r"(b0),"=r"(b1) : "r"(baddr));
                asm volatile("mma.sync.aligned.m16n8k16.row.col.f32.f16.f16.f32 "
                    "{%0,%1,%2,%3},{%4,%5,%6,%7},{%8,%9},{%0,%1,%2,%3};"
                    : "+f"(d[nt][0]),"+f"(d[nt][1]),"+f"(d[nt][2]),"+f"(d[nt][3])
                    : "r"(a0),"r"(a1),"r"(a2),"r"(a3),"r"(b0),"r"(b1));
            }
        }
    }
    int crow0 = wc*16 + (lane >> 2);
#pragma unroll
    for (int nt=0; nt<4; nt++) {
        int qc = q0 + wq*32 + nt*8 + (lane & 3)*2;
        g_o16[((size_t)(b*CC)+crow0)*NN + qc]       = __float2half(d[nt][0]);
        g_o16[((size_t)(b*CC)+crow0)*NN + qc + 1]   = __float2half(d[nt][1]);
        g_o16[((size_t)(b*CC)+crow0+8)*NN + qc]     = __float2half(d[nt][2]);
        g_o16[((size_t)(b*CC)+crow0+8)*NN + qc + 1] = __float2half(d[nt][3]);
    }
}

// ---------------- importance column sums -------------------------------------
__global__ __launch_bounds__(256) void imp_kernel() {
    int b = blockIdx.y;
    int m0 = blockIdx.x * 256;
    int t = threadIdx.x;
    __shared__ __half s_t[64][256];
    float acc = 0.f;
    for (int n0=0; n0<NN; n0+=64) {
        __syncthreads();
        for (int i=t; i<2048; i+=256) {
            int row = i >> 5, seg = i & 31;
            *reinterpret_cast<int4*>(&s_t[row][seg*8]) =
                *reinterpret_cast<const int4*>(&g_att[((size_t)(b*NN)+n0+row)*NN + m0 + seg*8]);
        }
        __syncthreads();
#pragma unroll 8
        for (int r=0;r<64;r++) acc += __half2float(s_t[r][t]);
    }
    g_imp[b*NN + m0 + t] = acc;
}

// ---------------- per-batch top-k via bitonic sort ----------------------------
__global__ void topk_kernel(float* __restrict__ outmask) {
    int b = blockIdx.x;
    int t = threadIdx.x;
    __shared__ unsigned long long sk[4096];
    for (int i=t;i<4096;i+=1024) {
        unsigned long long key;
        if (i < NN) {
            unsigned short hb = __half_as_ushort(__float2half(g_imp[b*NN+i]));
            key = ((unsigned long long)(0xFFFFu - (unsigned)hb) << 32) | (unsigned)i;
        } else key = 0xFFFFFFFFFFFFFFFFull;
        sk[i]=key;
    }
    __syncthreads();
    for (int k=2;k<=4096;k<<=1) {
        for (int j=k>>1;j>0;j>>=1) {
            for (int i=t;i<4096;i+=1024) {
                int ixj = i ^ j;
                if (ixj > i) {
                    bool up = ((i & k) == 0);
                    unsigned long long a = sk[i], c2 = sk[ixj];
                    if ((a > c2) == up) { sk[i]=c2; sk[ixj]=a; }
                }
            }
            __syncthreads();
        }
    }
    if (t < KSEL) g_idx[b*KSEL + t] = (int)(sk[t] & 0xFFFFFFFFull);
    for (int i=t;i<NN;i+=1024) outmask[b*NN + i] = 0.f;
    __syncthreads();
    if (t < KSEL) outmask[b*NN + (int)(sk[t] & 0xFFFFFFFFull)] = 1.0f;
}

// ---------------- gather q/k/v rows at selected indices -----------------------
__global__ void gather_kernel() {
    int g = blockIdx.x*256 + threadIdx.x;
    if (g >= BB*KSEL*CC) return;
    int c = g % CC; int bj = g / CC;
    int b = bj / KSEL;
    int n = g_idx[bj];
    g_vg[(size_t)bj*CC + c] = g_vtf[((size_t)(b*NN)+n)*CC + c];
    if (c < CQK) {
        g_qg[(size_t)bj*CQK + c] = g_qf [((size_t)(b*NN)+n)*CQK + c];
        g_kg[(size_t)bj*CQK + c] = g_ktf[((size_t)(b*NN)+n)*CQK + c];
    }
}

// ---------------- refinement softmax (fp32) -----------------------------------
__global__ void ar_kernel() {
    int b = blockIdx.y, kq = blockIdx.x;
    int t = threadIdx.x;
    int lane = t & 31, wid = t >> 5;
    __shared__ float s_q[16];
    __shared__ float s_red[4];
    if (t < 16) s_q[t] = g_qg[((size_t)(b*KSEL)+kq)*CQK + t];
    __syncthreads();
    float qv[16];
#pragma unroll
    for (int c=0;c<16;c++) qv[c]=s_q[c];

    float ev[5]; float lmax = -1e30f;
#pragma unroll
    for (int i=0;i<5;i++) {
        int j = t + i*128;
        float a = -1e30f;
        if (j < KSEL) {
            const float* kp = &g_kg[((size_t)(b*KSEL)+j)*CQK];
            a = 0.f;
#pragma unroll
            for (int c=0;c<16;c++) a += qv[c]*kp[c];
        }
        ev[i]=a; lmax = fmaxf(lmax, a);
    }
#pragma unroll
    for (int off=16;off;off>>=1) lmax = fmaxf(lmax, __shfl_xor_sync(0xFFFFFFFFu, lmax, off));
    if (lane==0) s_red[wid]=lmax;
    __syncthreads();
    float gmax = fmaxf(fmaxf(s_red[0],s_red[1]),fmaxf(s_red[2],s_red[3]));
    __syncthreads();
    float lsum = 0.f;
#pragma unroll
    for (int i=0;i<5;i++) {
        int j = t + i*128;
        if (j < KSEL) { float p = expf(ev[i]-gmax); ev[i]=p; lsum+=p; }
    }
#pragma unroll
    for (int off=16;off;off>>=1) lsum += __shfl_xor_sync(0xFFFFFFFFu, lsum, off);
    if (lane==0) s_red[wid]=lsum;
    __syncthreads();
    float gsum = s_red[0]+s_red[1]+s_red[2]+s_red[3];
#pragma unroll
    for (int i=0;i<5;i++) {
        int j = t + i*128;
        if (j < KSEL) g_ar[((size_t)(b*KSEL)+kq)*KSEL + j] = ev[i]/gsum;
    }
}

// ---------------- residual mix ------------------------------------------------
__global__ void mix_kernel(const float* __restrict__ gamma, int mode) {
    int i = blockIdx.x*256 + threadIdx.x;
    if (i >= BB*CC*NN) return;
    float g = gamma[0];
    float o = __half2float(g_o16[i]);
    float x = g_xact[i];
    float b16 = g*o + __half2float(__float2half(x));
    g_bbuf[i] = b16;
    if (mode == 2) g_bbuf2[i] = g*o + x;
}

// ---------------- fp32 refinement: overwrite b32 at top-k columns ------------
__global__ void refine_kernel(const float* __restrict__ gamma) {
    int b = blockIdx.y, kq = blockIdx.x;
    int t = threadIdx.x;  // 64 (= channel)
    __shared__ float s_ar[KSEL];
    for (int i=t;i<KSEL;i+=64) s_ar[i] = g_ar[((size_t)(b*KSEL)+kq)*KSEL+i];
    __syncthreads();
    float acc = 0.f;
    for (int j=0;j<KSEL;j++)
        acc += g_vg[((size_t)(b*KSEL)+j)*CC + t] * s_ar[j];
    int n = g_idx[b*KSEL+kq];
    float g = gamma[0];
    g_bbuf2[((size_t)(b*CC)+t)*NN + n] = g*acc + g_xact[((size_t)(b*CC)+t)*NN + n];
}

// ---------------- launcher ----------------------------------------------------
extern "C" void kernel_launch(void* const* d_in, const int* in_sizes, int n_in,
                              void* d_out, int out_size)
{
    (void)in_sizes; (void)n_in; (void)out_size;
    const float* x = (const float*)d_in[0];
    float* out = (float*)d_out;
    const int S = BB*CC*NN;
    float* out_s16  = out;
    float* out_s32  = out + S;
    float* out_mask = out + 2*S;

    pos_kernel<<<24, 256>>>();

    for (int L=0; L<2; L++) {
        int base = 1 + 11*L;
        const float* pre_w  = (const float*)d_in[base+0];
        const float* pre_bn = (const float*)d_in[base+1];
        const float* qw     = (const float*)d_in[base+2];
        const float* qb     = (const float*)d_in[base+3];
        const float* kw     = (const float*)d_in[base+4];
        const float* kb     = (const float*)d_in[base+5];
        const float* vw     = (const float*)d_in[base+6];
        const float* vb     = (const float*)d_in[base+7];
        const float* fin_w  = (const float*)d_in[base+8];
        const float* fin_bn = (const float*)d_in[base+9];
        const float* gamma  = (const float*)d_in[base+10];

        conv3x3_kernel<<<BB*HH*2, 256>>>(x, nullptr, pre_w, pre_bn,
                                         (L==0)?CIN0:CC, (L==0)?0:1, 0, 1);
        qkv_kernel<<<dim3(48,8), 256>>>(qw,qb,kw,kb,vw,vb);
        attn_kernel<<<dim3(NN/2,BB), 128>>>();
        out16_kernel<<<dim3(48,8), 256>>>();

        if (L==1) {
            imp_kernel<<<dim3(12,8), 256>>>();
            topk_kernel<<<8, 1024>>>(out_mask);
            gather_kernel<<<(BB*KSEL*CC+255)/256, 256>>>();
            ar_kernel<<<dim3(KSEL,BB), 128>>>();
        }

        mix_kernel<<<(S+255)/256, 256>>>(gamma, (L==1)?2:0);

        conv3x3_kernel<<<BB*HH*2, 256>>>(nullptr, (L==0)?nullptr:out_s16,
                                         fin_w, fin_bn, CC, 2, (L==0)?1:2, 2);

        if (L==1) {
            refine_kernel<<<dim3(KSEL,BB), 64>>>(gamma);
            conv3x3_kernel<<<BB*HH*2, 256>>>(nullptr, out_s32,
                                             fin_w, fin_bn, CC, 3, 2, 0);
        }
    }
}

// round 17
// speedup vs baseline: 1.5613x; 1.1083x over previous
#include <cuda_runtime.h>
#include <cuda_fp16.h>
#include <math.h>

#define BB 8
#define HH 32
#define WW 96
#define NN 3072      // HH*WW
#define CC 64
#define CQK 16
#define KSEL 614
#define CIN0 512
#define BN_EPS 1e-5f

// ---------------- device scratch (static allocation, allowed) ----------------
__device__ float  g_ptab[64*96];        // positional table (c, coord-1)
__device__ float  g_xact[BB*CC*NN];
__device__ float  g_chain[BB*CC*NN];
__device__ float  g_bbuf[BB*CC*NN];
__device__ float  g_bbuf2[BB*CC*NN];
__device__ float  g_qf [BB*NN*CQK];
__device__ float  g_ktf[BB*NN*CQK];
__device__ float  g_vtf[BB*NN*CC];
__device__ __half g_qh [BB*NN*CQK];
__device__ __half g_kh [BB*NN*CQK];
__device__ __half g_vh [BB*NN*CC];
__device__ __half g_att[(size_t)BB*NN*NN];  // 151 MB
__device__ __half g_o16[BB*CC*NN];
__device__ float  g_imp[BB*NN];
__device__ int    g_idx[BB*KSEL];
__device__ float  g_qg[BB*KSEL*CQK];
__device__ float  g_kg[BB*KSEL*CQK];
__device__ float  g_vg[BB*KSEL*CC];
__device__ float  g_ar[(size_t)BB*KSEL*KSEL];

// ---------------- positional table (same per-element double formula) ---------
__global__ void pos_kernel() {
    int i = blockIdx.x*blockDim.x + threadIdx.x;
    if (i >= 64*96) return;
    int c = i / 96, j = i % 96;
    int cc = c & 31;
    int ii = cc >> 1;
    double t = pow(10000.0, (double)ii / 16.0);
    double v = (double)(j+1) / t;
    double r = ((cc & 1) == 0) ? sin(v) : cos(v);
    g_ptab[i] = (float)r;
}

// ---------------- conv 3x3 (pad 1) + BN + ReLU (mask-critical fma chains) ----
// Round-13 configuration (best measured): 256 threads, thread = 4 cout x 6 px,
// grid = BB*HH. Pos added from table (bit-identical values).
__global__ __launch_bounds__(256) void conv3x3_kernel(
        const float* __restrict__ xin, float* __restrict__ outp,
        const float* __restrict__ w, const float* __restrict__ bn,
        int Cin, int src, int dst, int flags)
{
    const float* in = (src==0) ? xin : (src==1 ? g_chain : (src==2 ? g_bbuf : g_bbuf2));
    float* out = (dst==0) ? g_xact : (dst==1 ? g_chain : outp);

    int b = blockIdx.x / HH;
    int y = blockIdx.x % HH;
    int t = threadIdx.x;
    int pxg = t & 15, cog = t >> 4;    // 16 px-groups x 16 cout-groups
    int x0 = pxg * 6;

    __shared__ float s_in[8][3][98];
    __shared__ float s_w[8][64][9];
    __shared__ float s_inv[64], s_beta[64];

    if (t < 64) {
        float s = bn[t], bb = bn[64+t], m = bn[128+t], v = bn[192+t];
        float inv = s * rsqrtf(v + BN_EPS);
        s_inv[t] = inv;
        s_beta[t] = bb - m*inv;
    }

    float acc[4][6];
#pragma unroll
    for (int i=0;i<4;i++)
#pragma unroll
        for (int j=0;j<6;j++) acc[i][j]=0.f;

    for (int ci0 = 0; ci0 < Cin; ci0 += 8) {
        __syncthreads();
        for (int i=t; i<2352; i+=256) {
            int cc = i/294; int r = (i%294)/98; int col = i%98;
            int yy = y-1+r; int xx = col-1;
            float v = 0.f;
            if (yy>=0 && yy<HH && xx>=0 && xx<WW)
                v = in[((size_t)(b*Cin + ci0+cc)*HH + yy)*WW + xx];
            s_in[cc][r][col] = v;
        }
        for (int i=t; i<4608; i+=256) {
            int cc = i/576; int rem = i%576; int co = rem/9; int kk = rem%9;
            s_w[cc][co][kk] = w[((size_t)(co*Cin) + ci0+cc)*9 + kk];
        }
        __syncthreads();
#pragma unroll
        for (int cc=0; cc<8; cc++) {
            float iv[3][8];
#pragma unroll
            for (int r=0;r<3;r++)
#pragma unroll
                for (int j=0;j<8;j++)
                    iv[r][j] = s_in[cc][r][x0+j];
#pragma unroll
            for (int co8=0; co8<4; co8++) {
                const float* wp = s_w[cc][cog*4+co8];
                float w9[9];
#pragma unroll
                for (int k=0;k<9;k++) w9[k]=wp[k];
#pragma unroll
                for (int p=0;p<6;p++) {
                    float a = acc[co8][p];
                    a = __fmaf_rn(iv[0][p  ], w9[0], a);
                    a = __fmaf_rn(iv[0][p+1], w9[1], a);
                    a = __fmaf_rn(iv[0][p+2], w9[2], a);
                    a = __fmaf_rn(iv[1][p  ], w9[3], a);
                    a = __fmaf_rn(iv[1][p+1], w9[4], a);
                    a = __fmaf_rn(iv[1][p+2], w9[5], a);
                    a = __fmaf_rn(iv[2][p  ], w9[6], a);
                    a = __fmaf_rn(iv[2][p+1], w9[7], a);
                    a = __fmaf_rn(iv[2][p+2], w9[8], a);
                    acc[co8][p] = a;
                }
            }
        }
    }
#pragma unroll
    for (int co8=0; co8<4; co8++) {
        int co = cog*4 + co8;
        float inv = s_inv[co], beta = s_beta[co];
#pragma unroll
        for (int p=0;p<6;p++) {
            int x = x0 + p;
            float v = __fmaf_rn(acc[co8][p], inv, beta);
            v = fmaxf(v, 0.f);
            if (flags & 1) v += g_ptab[co*96 + ((co<32)? y : x)];
            if (flags & 2) v = __half2float(__float2half(v));
            out[((size_t)(b*CC + co)*HH + y)*WW + x] = v;
        }
    }
}

// ---------------- QKV projection ----------------------------------------------
__global__ void qkv_kernel(const float* __restrict__ qw, const float* __restrict__ qb,
                           const float* __restrict__ kw, const float* __restrict__ kb,
                           const float* __restrict__ vw, const float* __restrict__ vb)
{
    int b = blockIdx.y;
    int n0 = blockIdx.x * 64;
    int t = threadIdx.x;
    int nt = t & 63, og = t >> 6;     // 4 output groups of 24

    __shared__ float s_x[64][64];
    __shared__ float s_w[96][64];
    __shared__ float s_b[96];

    for (int i=t; i<64*64; i+=256) {
        int c = i>>6, nn2 = i&63;
        s_x[c][nn2] = g_xact[((size_t)(b*CC+c))*NN + n0 + nn2];
    }
    for (int i=t; i<96*64; i+=256) {
        int o = i>>6, c = i&63;
        float wv;
        if (o < 16)      wv = qw[o*64+c];
        else if (o < 32) wv = kw[(o-16)*64+c];
        else             wv = vw[(o-32)*64+c];
        s_w[o][c] = wv;
    }
    if (t < 96) s_b[t] = (t<16)? qb[t] : (t<32 ? kb[t-16] : vb[t-32]);
    __syncthreads();

    float xv[64];
#pragma unroll
    for (int c=0;c<64;c++) xv[c] = s_x[c][nt];

    int n = n0 + nt;
    for (int oi=0; oi<24; oi++) {
        int o = og*24 + oi;
        float a = s_b[o];
#pragma unroll
        for (int c4=0;c4<16;c4++) {
            float4 wv4 = *reinterpret_cast<const float4*>(&s_w[o][c4*4]);
            a = __fmaf_rn(wv4.x, xv[c4*4+0], a);
            a = __fmaf_rn(wv4.y, xv[c4*4+1], a);
            a = __fmaf_rn(wv4.z, xv[c4*4+2], a);
            a = __fmaf_rn(wv4.w, xv[c4*4+3], a);
        }
        if (o < 16) {
            g_qf[((size_t)(b*NN)+n)*CQK + o] = a;
            g_qh[((size_t)(b*NN)+n)*CQK + o] = __float2half(a);
        } else if (o < 32) {
            int oo = o-16;
            g_ktf[((size_t)(b*NN)+n)*CQK + oo] = a;
            g_kh [((size_t)(b*NN)+n)*CQK + oo] = __float2half(a);
        } else {
            int oo = o-32;
            g_vtf[((size_t)(b*NN)+n)*CC + oo] = a;
            g_vh [((size_t)(b*NN)+n)*CC + oo] = __float2half(a);
        }
    }
}

// ---------------- fused energy(fp16) + softmax(fp32) -> att(fp16) ------------
// Round-10 passing version (bit-frozen for the mask path).
__global__ __launch_bounds__(128) void attn_kernel()
{
    int b = blockIdx.y;
    int q0 = blockIdx.x * 2;
    int t = threadIdx.x;
    int lane = t & 31, wid = t >> 5;

    __shared__ float s_q[2][16];
    __shared__ float s_red[2][4];

    if (t < 32) s_q[t>>4][t&15] =
        __half2float(g_qh[((size_t)(b*NN)+q0+(t>>4))*CQK + (t&15)]);
    __syncthreads();
    float qa[16], qb[16];
#pragma unroll
    for (int c=0;c<16;c++) { qa[c]=s_q[0][c]; qb[c]=s_q[1][c]; }

    float ev0[24], ev1[24];
    float lmax0 = -1e30f, lmax1 = -1e30f;
    const int4* kp = reinterpret_cast<const int4*>(&g_kh[((size_t)(b*NN)+t)*CQK]);
#pragma unroll
    for (int i=0;i<24;i++) {
        int4 r0 = kp[0], r1 = kp[1];
        kp += 256;   // 128 rows * 32B / 16B
        __half h[16];
        *reinterpret_cast<int4*>(&h[0]) = r0;
        *reinterpret_cast<int4*>(&h[8]) = r1;
        float a0 = 0.f, a1 = 0.f;
#pragma unroll
        for (int c=0;c<16;c++) {
            float hf = __half2float(h[c]);
            a0 = __fmaf_rn(qa[c], hf, a0);
            a1 = __fmaf_rn(qb[c], hf, a1);
        }
        a0 = __half2float(__float2half(a0));   // energy stored as fp16 in ref
        a1 = __half2float(__float2half(a1));
        ev0[i] = a0; ev1[i] = a1;
        lmax0 = fmaxf(lmax0, a0);
        lmax1 = fmaxf(lmax1, a1);
    }
#pragma unroll
    for (int off=16;off;off>>=1) {
        lmax0 = fmaxf(lmax0, __shfl_xor_sync(0xFFFFFFFFu, lmax0, off));
        lmax1 = fmaxf(lmax1, __shfl_xor_sync(0xFFFFFFFFu, lmax1, off));
    }
    if (lane==0) { s_red[0][wid]=lmax0; s_red[1][wid]=lmax1; }
    __syncthreads();
    float gmax0 = fmaxf(fmaxf(s_red[0][0],s_red[0][1]),fmaxf(s_red[0][2],s_red[0][3]));
    float gmax1 = fmaxf(fmaxf(s_red[1][0],s_red[1][1]),fmaxf(s_red[1][2],s_red[1][3]));
    __syncthreads();

    float lsum0 = 0.f, lsum1 = 0.f;
#pragma unroll
    for (int i=0;i<24;i++) {
        float p0 = expf(ev0[i]-gmax0); ev0[i]=p0; lsum0+=p0;
        float p1 = expf(ev1[i]-gmax1); ev1[i]=p1; lsum1+=p1;
    }
#pragma unroll
    for (int off=16;off;off>>=1) {
        lsum0 += __shfl_xor_sync(0xFFFFFFFFu, lsum0, off);
        lsum1 += __shfl_xor_sync(0xFFFFFFFFu, lsum1, off);
    }
    if (lane==0) { s_red[0][wid]=lsum0; s_red[1][wid]=lsum1; }
    __syncthreads();
    float gsum0 = s_red[0][0]+s_red[0][1]+s_red[0][2]+s_red[0][3];
    float gsum1 = s_red[1][0]+s_red[1][1]+s_red[1][2]+s_red[1][3];

    __half* ap0 = &g_att[((size_t)(b*NN)+q0  )*NN + t];
    __half* ap1 = &g_att[((size_t)(b*NN)+q0+1)*NN + t];
#pragma unroll
    for (int i=0;i<24;i++) {
        ap0[i*128] = __float2half(ev0[i]/gsum0);
        ap1[i*128] = __float2half(ev1[i]/gsum1);
    }
}

// ---------------- out16 = V(fp16) @ att^T(fp16) via HMMA ----------------------
// Register-prefetch pipeline. o16 bits unchanged vs round-10 chain order.
__global__ __launch_bounds__(256) void out16_kernel()
{
    int b = blockIdx.y;
    int q0 = blockIdx.x * 64;
    int t = threadIdx.x, lane = t & 31, warp = t >> 5;
    int wc = warp & 3;        // c tile: 16 rows
    int wq = warp >> 2;       // q half: 32 cols

    __shared__ __half s_v[64][72];
    __shared__ __half s_a[64][72];
    unsigned svb = (unsigned)__cvta_generic_to_shared(&s_v[0][0]);
    unsigned sab = (unsigned)__cvta_generic_to_shared(&s_a[0][0]);

    float d[4][4];
#pragma unroll
    for (int i=0;i<4;i++)
#pragma unroll
        for (int j=0;j<4;j++) d[i][j]=0.f;

    int mrelA = (lane & 7) + ((lane >> 4) << 3);
    int crelA = wc*16 + ((lane >> 3) & 1) * 8;
    int qrelB = wq*32 + (lane & 7);
    int mrelB = ((lane >> 3) & 1) * 8;

    int row0 = t >> 3, seg = t & 7;    // i = t
    int row1 = row0 + 32;              // i = t + 256

    int4 rv0, rv1, ra0, ra1;
    rv0 = *reinterpret_cast<const int4*>(&g_vh[((size_t)(b*NN)+row0)*CC + seg*8]);
    rv1 = *reinterpret_cast<const int4*>(&g_vh[((size_t)(b*NN)+row1)*CC + seg*8]);
    ra0 = *reinterpret_cast<const int4*>(&g_att[((size_t)(b*NN)+q0+row0)*NN + seg*8]);
    ra1 = *reinterpret_cast<const int4*>(&g_att[((size_t)(b*NN)+q0+row1)*NN + seg*8]);

    for (int it=0; it<48; it++) {
        __syncthreads();
        *reinterpret_cast<int4*>(&s_v[row0][seg*8]) = rv0;
        *reinterpret_cast<int4*>(&s_v[row1][seg*8]) = rv1;
        *reinterpret_cast<int4*>(&s_a[row0][seg*8]) = ra0;
        *reinterpret_cast<int4*>(&s_a[row1][seg*8]) = ra1;
        __syncthreads();
        if (it+1 < 48) {
            int m1 = (it+1)*64;
            rv0 = *reinterpret_cast<const int4*>(&g_vh[((size_t)(b*NN)+m1+row0)*CC + seg*8]);
            rv1 = *reinterpret_cast<const int4*>(&g_vh[((size_t)(b*NN)+m1+row1)*CC + seg*8]);
            ra0 = *reinterpret_cast<const int4*>(&g_att[((size_t)(b*NN)+q0+row0)*NN + m1 + seg*8]);
            ra1 = *reinterpret_cast<const int4*>(&g_att[((size_t)(b*NN)+q0+row1)*NN + m1 + seg*8]);
        }
#pragma unroll
        for (int ks=0; ks<4; ks++) {
            int mk = ks*16;
            unsigned aaddr = svb + (unsigned)(((mk + mrelA)*72 + crelA)*2);
            unsigned a0,a1,a2,a3;
            asm volatile("ldmatrix.sync.aligned.m8n8.x4.trans.shared.b16 {%0,%1,%2,%3},[%4];"
                : "=r"(a0),"=r"(a1),"=r"(a2),"=r"(a3) : "r"(aaddr));
#pragma unroll
            for (int nt=0; nt<4; nt++) {
                unsigned baddr = sab + (unsigned)(((qrelB + nt*8)*72 + mk + mrelB)*2);
                unsigned b0,b1;
                asm volatile("ldmatrix.sync.aligned.m8n8.x2.shared.b16 {%0,%1},[%2];"
                    : "=r"(b0),"=r"(b1) : "r"(baddr));
                asm volatile("mma.sync.aligned.m16n8k16.row.col.f32.f16.f16.f32 "
                    "{%0,%1,%2,%3},{%4,%5,%6,%7},{%8,%9},{%0,%1,%2,%3};"
                    : "+f"(d[nt][0]),"+f"(d[nt][1]),"+f"(d[nt][2]),"+f"(d[nt][3])
                    : "r"(a0),"r"(a1),"r"(a2),"r"(a3),"r"(b0),"r"(b1));
            }
        }
    }
    int crow0 = wc*16 + (lane >> 2);
#pragma unroll
    for (int nt=0; nt<4; nt++) {
        int qc = q0 + wq*32 + nt*8 + (lane & 3)*2;
        g_o16[((size_t)(b*CC)+crow0)*NN + qc]       = __float2half(d[nt][0]);
        g_o16[((size_t)(b*CC)+crow0)*NN + qc + 1]   = __float2half(d[nt][1]);
        g_o16[((size_t)(b*CC)+crow0+8)*NN + qc]     = __float2half(d[nt][2]);
        g_o16[((size_t)(b*CC)+crow0+8)*NN + qc + 1] = __float2half(d[nt][3]);
    }
}

// ---------------- importance column sums -------------------------------------
__global__ __launch_bounds__(256) void imp_kernel() {
    int b = blockIdx.y;
    int m0 = blockIdx.x * 256;
    int t = threadIdx.x;
    __shared__ __half s_t[64][256];
    float acc = 0.f;
    for (int n0=0; n0<NN; n0+=64) {
        __syncthreads();
        for (int i=t; i<2048; i+=256) {
            int row = i >> 5, seg = i & 31;
            *reinterpret_cast<int4*>(&s_t[row][seg*8]) =
                *reinterpret_cast<const int4*>(&g_att[((size_t)(b*NN)+n0+row)*NN + m0 + seg*8]);
        }
        __syncthreads();
#pragma unroll 8
        for (int r=0;r<64;r++) acc += __half2float(s_t[r][t]);
    }
    g_imp[b*NN + m0 + t] = acc;
}

// ---------------- per-batch top-k via bitonic sort ----------------------------
__global__ void topk_kernel(float* __restrict__ outmask) {
    int b = blockIdx.x;
    int t = threadIdx.x;
    __shared__ unsigned long long sk[4096];
    for (int i=t;i<4096;i+=1024) {
        unsigned long long key;
        if (i < NN) {
            unsigned short hb = __half_as_ushort(__float2half(g_imp[b*NN+i]));
            key = ((unsigned long long)(0xFFFFu - (unsigned)hb) << 32) | (unsigned)i;
        } else key = 0xFFFFFFFFFFFFFFFFull;
        sk[i]=key;
    }
    __syncthreads();
    for (int k=2;k<=4096;k<<=1) {
        for (int j=k>>1;j>0;j>>=1) {
            for (int i=t;i<4096;i+=1024) {
                int ixj = i ^ j;
                if (ixj > i) {
                    bool up = ((i & k) == 0);
                    unsigned long long a = sk[i], c2 = sk[ixj];
                    if ((a > c2) == up) { sk[i]=c2; sk[ixj]=a; }
                }
            }
            __syncthreads();
        }
    }
    if (t < KSEL) g_idx[b*KSEL + t] = (int)(sk[t] & 0xFFFFFFFFull);
    for (int i=t;i<NN;i+=1024) outmask[b*NN + i] = 0.f;
    __syncthreads();
    if (t < KSEL) outmask[b*NN + (int)(sk[t] & 0xFFFFFFFFull)] = 1.0f;
}

// ---------------- gather q/k/v rows at selected indices -----------------------
__global__ void gather_kernel() {
    int g = blockIdx.x*256 + threadIdx.x;
    if (g >= BB*KSEL*CC) return;
    int c = g % CC; int bj = g / CC;
    int b = bj / KSEL;
    int n = g_idx[bj];
    g_vg[(size_t)bj*CC + c] = g_vtf[((size_t)(b*NN)+n)*CC + c];
    if (c < CQK) {
        g_qg[(size_t)bj*CQK + c] = g_qf [((size_t)(b*NN)+n)*CQK + c];
        g_kg[(size_t)bj*CQK + c] = g_ktf[((size_t)(b*NN)+n)*CQK + c];
    }
}

// ---------------- refinement softmax (fp32) -----------------------------------
__global__ void ar_kernel() {
    int b = blockIdx.y, kq = blockIdx.x;
    int t = threadIdx.x;
    int lane = t & 31, wid = t >> 5;
    __shared__ float s_q[16];
    __shared__ float s_red[4];
    if (t < 16) s_q[t] = g_qg[((size_t)(b*KSEL)+kq)*CQK + t];
    __syncthreads();
    float qv[16];
#pragma unroll
    for (int c=0;c<16;c++) qv[c]=s_q[c];

    float ev[5]; float lmax = -1e30f;
#pragma unroll
    for (int i=0;i<5;i++) {
        int j = t + i*128;
        float a = -1e30f;
        if (j < KSEL) {
            const float* kp = &g_kg[((size_t)(b*KSEL)+j)*CQK];
            a = 0.f;
#pragma unroll
            for (int c=0;c<16;c++) a += qv[c]*kp[c];
        }
        ev[i]=a; lmax = fmaxf(lmax, a);
    }
#pragma unroll
    for (int off=16;off;off>>=1) lmax = fmaxf(lmax, __shfl_xor_sync(0xFFFFFFFFu, lmax, off));
    if (lane==0) s_red[wid]=lmax;
    __syncthreads();
    float gmax = fmaxf(fmaxf(s_red[0],s_red[1]),fmaxf(s_red[2],s_red[3]));
    __syncthreads();
    float lsum = 0.f;
#pragma unroll
    for (int i=0;i<5;i++) {
        int j = t + i*128;
        if (j < KSEL) { float p = expf(ev[i]-gmax); ev[i]=p; lsum+=p; }
    }
#pragma unroll
    for (int off=16;off;off>>=1) lsum += __shfl_xor_sync(0xFFFFFFFFu, lsum, off);
    if (lane==0) s_red[wid]=lsum;
    __syncthreads();
    float gsum = s_red[0]+s_red[1]+s_red[2]+s_red[3];
#pragma unroll
    for (int i=0;i<5;i++) {
        int j = t + i*128;
        if (j < KSEL) g_ar[((size_t)(b*KSEL)+kq)*KSEL + j] = ev[i]/gsum;
    }
}

// ---------------- residual mix ------------------------------------------------
__global__ void mix_kernel(const float* __restrict__ gamma, int mode) {
    int i = blockIdx.x*256 + threadIdx.x;
    if (i >= BB*CC*NN) return;
    float g = gamma[0];
    float o = __half2float(g_o16[i]);
    float x = g_xact[i];
    float b16 = g*o + __half2float(__float2half(x));
    g_bbuf[i] = b16;
    if (mode == 2) g_bbuf2[i] = g*o + x;
}

// ---------------- fp32 refinement: overwrite b32 at top-k columns ------------
__global__ void refine_kernel(const float* __restrict__ gamma) {
    int b = blockIdx.y, kq = blockIdx.x;
    int t = threadIdx.x;  // 64 (= channel)
    __shared__ float s_ar[KSEL];
    for (int i=t;i<KSEL;i+=64) s_ar[i] = g_ar[((size_t)(b*KSEL)+kq)*KSEL+i];
    __syncthreads();
    float acc = 0.f;
    for (int j=0;j<KSEL;j++)
        acc += g_vg[((size_t)(b*KSEL)+j)*CC + t] * s_ar[j];
    int n = g_idx[b*KSEL+kq];
    float g = gamma[0];
    g_bbuf2[((size_t)(b*CC)+t)*NN + n] = g*acc + g_xact[((size_t)(b*CC)+t)*NN + n];
}

// ---------------- launcher ----------------------------------------------------
extern "C" void kernel_launch(void* const* d_in, const int* in_sizes, int n_in,
                              void* d_out, int out_size)
{
    (void)in_sizes; (void)n_in; (void)out_size;
    const float* x = (const float*)d_in[0];
    float* out = (float*)d_out;
    const int S = BB*CC*NN;
    float* out_s16  = out;
    float* out_s32  = out + S;
    float* out_mask = out + 2*S;

    pos_kernel<<<24, 256>>>();

    for (int L=0; L<2; L++) {
        int base = 1 + 11*L;
        const float* pre_w  = (const float*)d_in[base+0];
        const float* pre_bn = (const float*)d_in[base+1];
        const float* qw     = (const float*)d_in[base+2];
        const float* qb     = (const float*)d_in[base+3];
        const float* kw     = (const float*)d_in[base+4];
        const float* kb     = (const float*)d_in[base+5];
        const float* vw     = (const float*)d_in[base+6];
        const float* vb     = (const float*)d_in[base+7];
        const float* fin_w  = (const float*)d_in[base+8];
        const float* fin_bn = (const float*)d_in[base+9];
        const float* gamma  = (const float*)d_in[base+10];

        conv3x3_kernel<<<BB*HH, 256>>>(x, nullptr, pre_w, pre_bn,
                                       (L==0)?CIN0:CC, (L==0)?0:1, 0, 1);
        qkv_kernel<<<dim3(48,8), 256>>>(qw,qb,kw,kb,vw,vb);
        attn_kernel<<<dim3(NN/2,BB), 128>>>();
        out16_kernel<<<dim3(48,8), 256>>>();

        if (L==1) {
            imp_kernel<<<dim3(12,8), 256>>>();
            topk_kernel<<<8, 1024>>>(out_mask);
            gather_kernel<<<(BB*KSEL*CC+255)/256, 256>>>();
            ar_kernel<<<dim3(KSEL,BB), 128>>>();
        }

        mix_kernel<<<(S+255)/256, 256>>>(gamma, (L==1)?2:0);

        conv3x3_kernel<<<BB*HH, 256>>>(nullptr, (L==0)?nullptr:out_s16,
                                       fin_w, fin_bn, CC, 2, (L==0)?1:2, 2);

        if (L==1) {
            refine_kernel<<<dim3(KSEL,BB), 64>>>(gamma);
            conv3x3_kernel<<<BB*HH, 256>>>(nullptr, out_s32,
                                           fin_w, fin_bn, CC, 3, 2, 0);
        }
    }
}